// round 2
// baseline (speedup 1.0000x reference)
#include <cuda_runtime.h>
#include <math.h>

// Problem shape (fixed by setup_inputs): B=64, H=W=24, D=1024, S=577
#define B_   64
#define H_   24
#define W_   24
#define D_   1024
#define S_   (1 + H_*W_)          // 577
#define SD_  (S_ * D_)            // 590848
#define SD4_ (SD_ / 4)            // 147712

#define OMEGA1 2.62205755429212
#define LIM_T  5000.0f
#define LIM_WP 10000.0f
#define NEAR_  1.5e-7f

// Reduce 4 values with a single barrier pair. 256 threads = 8 warps.
__device__ __forceinline__ void block_reduce4(float& a, float& b, float& c, float& d,
                                              float (*sh)[4]) {
    #pragma unroll
    for (int o = 16; o > 0; o >>= 1) {
        a += __shfl_down_sync(0xffffffffu, a, o);
        b += __shfl_down_sync(0xffffffffu, b, o);
        c += __shfl_down_sync(0xffffffffu, c, o);
        d += __shfl_down_sync(0xffffffffu, d, o);
    }
    int w = threadIdx.x >> 5, l = threadIdx.x & 31;
    if (l == 0) { sh[w][0] = a; sh[w][1] = b; sh[w][2] = c; sh[w][3] = d; }
    __syncthreads();
    if (w == 0 && l < 8) {
        a = sh[l][0]; b = sh[l][1]; c = sh[l][2]; d = sh[l][3];
        #pragma unroll
        for (int o = 4; o > 0; o >>= 1) {
            a += __shfl_down_sync(0xffu, a, o);
            b += __shfl_down_sync(0xffu, b, o);
            c += __shfl_down_sync(0xffu, c, o);
            d += __shfl_down_sync(0xffu, d, o);
        }
        if (l == 0) { sh[0][0] = a; sh[0][1] = b; sh[0][2] = c; sh[0][3] = d; }
    }
    __syncthreads();
    a = sh[0][0]; b = sh[0][1]; c = sh[0][2]; d = sh[0][3];
    __syncthreads();
}

__global__ __launch_bounds__(256)
void fused_pos_add_kernel(const float4* __restrict__ x,
                          float4* __restrict__ out,
                          const float* __restrict__ log_alpha_scale,
                          const float* __restrict__ alpha_learn,
                          const float4* __restrict__ proj_w,   // [4, D]
                          const float4* __restrict__ proj_b,   // [D]
                          const float4* __restrict__ ln_g,     // [D]
                          const float4* __restrict__ ln_b,     // [D]
                          const float4* __restrict__ cls_pos,  // [D]
                          const float* __restrict__ pos_scale)
{
    __shared__ float sh_red[8][4];
    __shared__ float sh_feats[4];

    const int s   = blockIdx.x;      // 0 = cls, 1..576 = patch rows
    const int tid = threadIdx.x;     // 0..255, one float4 (4 dims) per thread
    const float pscale = pos_scale[0];

    float4 posv;

    if (s == 0) {
        float4 c = cls_pos[tid];
        posv.x = c.x * pscale; posv.y = c.y * pscale;
        posv.z = c.z * pscale; posv.w = c.w * pscale;
    } else {
        const int idx = s - 1;
        const int pr = idx / W_;
        const int pc = idx % W_;

        // omega_3p = clip(softplus(alpha_learn), 0.02, 8.0)
        float al = alpha_learn[0];
        float sp = (al > 20.0f) ? al : log1pf(expf(al));
        float omega3p = fminf(fmaxf(sp, 0.02f), 8.0f);

        const float u = (pc + 0.5f) / (float)W_;
        const float v = (pr + 0.5f) / (float)H_;
        const float zr = u * (2.0f * (float)OMEGA1) * 0.4f;
        const float zi = v * (2.0f * omega3p) * 0.4f;

        // Lattice sum over m,n in [-12,12] \ {(0,0)}: 624 points
        float s1r = 0.f, s1i = 0.f, s2r = 0.f, s2i = 0.f;
        for (int k = tid; k < 625; k += 256) {
            int m = k / 25 - 12;
            int n = k % 25 - 12;
            if (m == 0 && n == 0) continue;
            float wr = 2.0f * (float)m * (float)OMEGA1;
            float wi = 2.0f * (float)n * (float)OMEGA1;
            float dr = zr - wr, di = zi - wi;
            float n2 = dr * dr + di * di;
            if (n2 <= NEAR_ * NEAR_) continue;   // reference mask (never active)
            float inv  = 1.0f / n2;
            float inv2 = inv * inv;
            float d2r = dr * dr - di * di;
            float d2i = 2.0f * dr * di;
            float t1r = d2r * inv2;
            float t1i = -d2i * inv2;
            float wn2 = wr * wr + wi * wi;
            float winv2 = 1.0f / (wn2 * wn2);
            t1r -= (wr * wr - wi * wi) * winv2;
            t1i += (2.0f * wr * wi) * winv2;
            t1r = fminf(fmaxf(t1r, -LIM_T), LIM_T);
            t1i = fminf(fmaxf(t1i, -LIM_T), LIM_T);
            float d3r = d2r * dr - d2i * di;
            float d3i = d2r * di + d2i * dr;
            float inv3 = inv2 * inv;
            float t2r = -2.0f * d3r * inv3;
            float t2i =  2.0f * d3i * inv3;
            t2r = fminf(fmaxf(t2r, -LIM_T), LIM_T);
            t2i = fminf(fmaxf(t2i, -LIM_T), LIM_T);
            s1r += t1r; s1i += t1i;
            s2r += t2r; s2i += t2i;
        }
        block_reduce4(s1r, s1i, s2r, s2i, sh_red);

        if (tid == 0) {
            float wpr, wpi, wppr, wppi;
            float zn2 = zr * zr + zi * zi;
            if (zn2 < NEAR_ * NEAR_) {
                wpr = 500.0f; wpi = 0.0f; wppr = 500.0f; wppi = 0.0f;
            } else {
                float zinv  = 1.0f / zn2;
                float zinv2 = zinv * zinv;
                float z2r = zr * zr - zi * zi;
                float z2i = 2.0f * zr * zi;
                wpr = z2r * zinv2 + s1r;
                wpi = -z2i * zinv2 + s1i;
                float z3r = z2r * zr - z2i * zi;
                float z3i = z2r * zi + z2i * zr;
                float zinv3 = zinv2 * zinv;
                wppr = -2.0f * z3r * zinv3 + s2r;
                wppi =  2.0f * z3i * zinv3 + s2i;
            }
            wpr  = fminf(fmaxf(wpr,  -LIM_WP), LIM_WP);
            wpi  = fminf(fmaxf(wpi,  -LIM_WP), LIM_WP);
            wppr = fminf(fmaxf(wppr, -LIM_WP), LIM_WP);
            wppi = fminf(fmaxf(wppi, -LIM_WP), LIM_WP);

            float alpha = fminf(fmaxf(expf(log_alpha_scale[0]), 0.002f), 0.8f);
            sh_feats[0] = tanhf(alpha * wpr);
            sh_feats[1] = tanhf(alpha * wpi);
            sh_feats[2] = tanhf(alpha * wppr);
            sh_feats[3] = tanhf(alpha * wppi);
        }
        __syncthreads();

        const float f0 = sh_feats[0], f1 = sh_feats[1],
                    f2 = sh_feats[2], f3 = sh_feats[3];

        // p = feats @ proj_w + proj_b  (this thread's 4 dims)
        float4 w0 = proj_w[tid];
        float4 w1 = proj_w[256 + tid];
        float4 w2 = proj_w[512 + tid];
        float4 w3 = proj_w[768 + tid];
        float4 bb = proj_b[tid];
        float4 p;
        p.x = f0 * w0.x + f1 * w1.x + f2 * w2.x + f3 * w3.x + bb.x;
        p.y = f0 * w0.y + f1 * w1.y + f2 * w2.y + f3 * w3.y + bb.y;
        p.z = f0 * w0.z + f1 * w1.z + f2 * w2.z + f3 * w3.z + bb.z;
        p.w = f0 * w0.w + f1 * w1.w + f2 * w2.w + f3 * w3.w + bb.w;

        // LayerNorm over D=1024
        float lsum = p.x + p.y + p.z + p.w;
        float lsq  = p.x*p.x + p.y*p.y + p.z*p.z + p.w*p.w;
        float dummy0 = 0.f, dummy1 = 0.f;
        block_reduce4(lsum, lsq, dummy0, dummy1, sh_red);
        float mean = lsum * (1.0f / D_);
        float var  = lsq * (1.0f / D_) - mean * mean;
        float rstd = rsqrtf(var + 1e-5f);

        float4 g = ln_g[tid];
        float4 b2 = ln_b[tid];
        posv.x = ((p.x - mean) * rstd * g.x + b2.x) * pscale;
        posv.y = ((p.y - mean) * rstd * g.y + b2.y) * pscale;
        posv.z = ((p.z - mean) * rstd * g.z + b2.z) * pscale;
        posv.w = ((p.w - mean) * rstd * g.w + b2.w) * pscale;
    }

    // Stream: out[b, s, :] = x[b, s, :] + posv  for all 64 batches
    const long long base = (long long)s * 256 + tid;   // float4 index
    #pragma unroll 8
    for (int b = 0; b < B_; ++b) {
        long long gi = (long long)b * SD4_ + base;
        float4 xv = __ldcs(x + gi);
        xv.x += posv.x; xv.y += posv.y; xv.z += posv.z; xv.w += posv.w;
        __stcs(out + gi, xv);
    }
}

extern "C" void kernel_launch(void* const* d_in, const int* in_sizes, int n_in,
                              void* d_out, int out_size)
{
    // metadata order: x, h, w, log_alpha_scale, alpha_learn, proj_w, proj_b,
    //                 ln_g, ln_b, cls_pos, pos_scale
    const float* x    = (const float*)d_in[0];
    const float* las  = (const float*)d_in[3];
    const float* al   = (const float*)d_in[4];
    const float* pw   = (const float*)d_in[5];
    const float* pb   = (const float*)d_in[6];
    const float* lg   = (const float*)d_in[7];
    const float* lb   = (const float*)d_in[8];
    const float* cls  = (const float*)d_in[9];
    const float* psc  = (const float*)d_in[10];

    fused_pos_add_kernel<<<S_, 256>>>((const float4*)x, (float4*)d_out,
                                      las, al,
                                      (const float4*)pw, (const float4*)pb,
                                      (const float4*)lg, (const float4*)lb,
                                      (const float4*)cls, psc);
}

// round 9
// speedup vs baseline: 1.0719x; 1.0719x over previous
#include <cuda_runtime.h>
#include <math.h>

// Problem shape (fixed by setup_inputs): B=64, H=W=24, D=1024, S=577
#define B_   64
#define H_   24
#define W_   24
#define D_   1024
#define S_   (1 + H_*W_)          // 577
#define SD_  (S_ * D_)            // 590848
#define SD4_ (SD_ / 4)            // 147712 = 577 * 256 exactly

#define OMEGA1 2.62205755429212
#define LIM_T  5000.0f
#define LIM_WP 10000.0f
#define NEAR_  1.5e-7f

// Positional table scratch: [S, D] floats (already scaled by pos_scale)
__device__ float g_pos[SD_];

// Warp allreduce (butterfly): every lane ends with the full sum.
__device__ __forceinline__ float warp_allreduce(float v) {
    #pragma unroll
    for (int o = 16; o > 0; o >>= 1) v += __shfl_xor_sync(0xffffffffu, v, o);
    return v;
}

// One WARP builds one pos row. No __syncthreads anywhere.
// grid = 73 blocks x 256 threads = 584 warps (last 7 idle), rows 0..576.
__global__ __launch_bounds__(256)
void build_pos_kernel(const float* __restrict__ log_alpha_scale,
                      const float* __restrict__ alpha_learn,
                      const float4* __restrict__ proj_w,   // [4, D] as float4
                      const float4* __restrict__ proj_b,
                      const float4* __restrict__ ln_g,
                      const float4* __restrict__ ln_b,
                      const float4* __restrict__ cls_pos,
                      const float* __restrict__ pos_scale)
{
    const int warp = (blockIdx.x * 256 + threadIdx.x) >> 5;   // global warp id
    const int lane = threadIdx.x & 31;
    if (warp >= S_) return;

    const float pscale = pos_scale[0];
    float4* pos4 = reinterpret_cast<float4*>(g_pos);

    if (warp == 0) {
        // cls row: D_/4 = 256 float4, 8 per lane
        #pragma unroll
        for (int i = lane; i < 256; i += 32) {
            float4 c = cls_pos[i];
            c.x *= pscale; c.y *= pscale; c.z *= pscale; c.w *= pscale;
            pos4[i] = c;
        }
        return;
    }

    const int idx = warp - 1;
    const int pr = idx / W_;
    const int pc = idx % W_;

    // omega_3p = clip(softplus(alpha_learn), 0.02, 8.0)
    float al = alpha_learn[0];
    float sp = (al > 20.0f) ? al : log1pf(expf(al));
    float omega3p = fminf(fmaxf(sp, 0.02f), 8.0f);

    const float u = (pc + 0.5f) / (float)W_;
    const float v = (pr + 0.5f) / (float)H_;
    const float zr = u * (2.0f * (float)OMEGA1) * 0.4f;
    const float zi = v * (2.0f * omega3p) * 0.4f;

    // Lattice sum over m,n in [-12,12] \ {(0,0)}: 624 points, ~20 per lane
    float s1r = 0.f, s1i = 0.f, s2r = 0.f, s2i = 0.f;
    for (int k = lane; k < 625; k += 32) {
        int m = k / 25 - 12;
        int n = k % 25 - 12;
        if (m == 0 && n == 0) continue;
        float wr = 2.0f * (float)m * (float)OMEGA1;
        float wi = 2.0f * (float)n * (float)OMEGA1;
        float dr = zr - wr, di = zi - wi;
        float n2 = dr * dr + di * di;
        if (n2 <= NEAR_ * NEAR_) continue;   // reference mask (never active)
        float inv  = 1.0f / n2;
        float inv2 = inv * inv;
        float d2r = dr * dr - di * di;
        float d2i = 2.0f * dr * di;
        float t1r = d2r * inv2;
        float t1i = -d2i * inv2;
        float wn2 = wr * wr + wi * wi;
        float winv2 = 1.0f / (wn2 * wn2);
        t1r -= (wr * wr - wi * wi) * winv2;
        t1i += (2.0f * wr * wi) * winv2;
        t1r = fminf(fmaxf(t1r, -LIM_T), LIM_T);
        t1i = fminf(fmaxf(t1i, -LIM_T), LIM_T);
        float d3r = d2r * dr - d2i * di;
        float d3i = d2r * di + d2i * dr;
        float inv3 = inv2 * inv;
        float t2r = -2.0f * d3r * inv3;
        float t2i =  2.0f * d3i * inv3;
        t2r = fminf(fmaxf(t2r, -LIM_T), LIM_T);
        t2i = fminf(fmaxf(t2i, -LIM_T), LIM_T);
        s1r += t1r; s1i += t1i;
        s2r += t2r; s2i += t2i;
    }
    s1r = warp_allreduce(s1r);
    s1i = warp_allreduce(s1i);
    s2r = warp_allreduce(s2r);
    s2i = warp_allreduce(s2i);

    // Finish wp / wp' (every lane computes the same values — cheap)
    float zn2 = zr * zr + zi * zi;          // z != 0 for all patch rows
    float zinv  = 1.0f / zn2;
    float zinv2 = zinv * zinv;
    float z2r = zr * zr - zi * zi;
    float z2i = 2.0f * zr * zi;
    float wpr = z2r * zinv2 + s1r;
    float wpi = -z2i * zinv2 + s1i;
    float z3r = z2r * zr - z2i * zi;
    float z3i = z2r * zi + z2i * zr;
    float zinv3 = zinv2 * zinv;
    float wppr = -2.0f * z3r * zinv3 + s2r;
    float wppi =  2.0f * z3i * zinv3 + s2i;

    wpr  = fminf(fmaxf(wpr,  -LIM_WP), LIM_WP);
    wpi  = fminf(fmaxf(wpi,  -LIM_WP), LIM_WP);
    wppr = fminf(fmaxf(wppr, -LIM_WP), LIM_WP);
    wppi = fminf(fmaxf(wppi, -LIM_WP), LIM_WP);

    float alpha = fminf(fmaxf(expf(log_alpha_scale[0]), 0.002f), 0.8f);
    const float f0 = tanhf(alpha * wpr);
    const float f1 = tanhf(alpha * wpi);
    const float f2 = tanhf(alpha * wppr);
    const float f3 = tanhf(alpha * wppi);

    // Projection: p = feats @ proj_w + proj_b.  Each lane owns 8 float4 chunks.
    float4 preg[8];
    float lsum = 0.f, lsq = 0.f;
    #pragma unroll
    for (int c = 0; c < 8; ++c) {
        int i = c * 32 + lane;               // float4 index in [0,256)
        float4 w0 = proj_w[i];
        float4 w1 = proj_w[256 + i];
        float4 w2 = proj_w[512 + i];
        float4 w3 = proj_w[768 + i];
        float4 bb = proj_b[i];
        float4 p;
        p.x = f0 * w0.x + f1 * w1.x + f2 * w2.x + f3 * w3.x + bb.x;
        p.y = f0 * w0.y + f1 * w1.y + f2 * w2.y + f3 * w3.y + bb.y;
        p.z = f0 * w0.z + f1 * w1.z + f2 * w2.z + f3 * w3.z + bb.z;
        p.w = f0 * w0.w + f1 * w1.w + f2 * w2.w + f3 * w3.w + bb.w;
        preg[c] = p;
        lsum += p.x + p.y + p.z + p.w;
        lsq  += p.x * p.x + p.y * p.y + p.z * p.z + p.w * p.w;
    }
    lsum = warp_allreduce(lsum);
    lsq  = warp_allreduce(lsq);
    float mean = lsum * (1.0f / D_);
    float var  = lsq * (1.0f / D_) - mean * mean;
    float rstd = rsqrtf(var + 1e-5f);

    float4* outrow = pos4 + warp * 256;
    #pragma unroll
    for (int c = 0; c < 8; ++c) {
        int i = c * 32 + lane;
        float4 g = ln_g[i];
        float4 b = ln_b[i];
        float4 p = preg[c];
        float4 o;
        o.x = ((p.x - mean) * rstd * g.x + b.x) * pscale;
        o.y = ((p.y - mean) * rstd * g.y + b.y) * pscale;
        o.z = ((p.z - mean) * rstd * g.z + b.z) * pscale;
        o.w = ((p.w - mean) * rstd * g.w + b.w) * pscale;
        outrow[i] = o;
    }
}

// Proven streaming add (R1 config) + .cs hints on the 302MB stream.
__global__ __launch_bounds__(256)
void add_pos_kernel(const float4* __restrict__ x, float4* __restrict__ out)
{
    const int b = blockIdx.y;
    const int i = blockIdx.x * 256 + threadIdx.x;   // float4 index within a batch
    if (i >= SD4_) return;
    const long long gi = (long long)b * SD4_ + i;
    float4 xv = __ldcs(x + gi);
    float4 pv = reinterpret_cast<const float4*>(g_pos)[i];
    xv.x += pv.x; xv.y += pv.y; xv.z += pv.z; xv.w += pv.w;
    __stcs(out + gi, xv);
}

extern "C" void kernel_launch(void* const* d_in, const int* in_sizes, int n_in,
                              void* d_out, int out_size)
{
    // metadata order: x, h, w, log_alpha_scale, alpha_learn, proj_w, proj_b,
    //                 ln_g, ln_b, cls_pos, pos_scale
    const float* x    = (const float*)d_in[0];
    const float* las  = (const float*)d_in[3];
    const float* al   = (const float*)d_in[4];
    const float* pw   = (const float*)d_in[5];
    const float* pb   = (const float*)d_in[6];
    const float* lg   = (const float*)d_in[7];
    const float* lb   = (const float*)d_in[8];
    const float* cls  = (const float*)d_in[9];
    const float* psc  = (const float*)d_in[10];

    // 577 rows, one warp each: 73 blocks x 8 warps = 584 warps
    build_pos_kernel<<<(S_ + 7) / 8, 256>>>(las, al,
                                            (const float4*)pw, (const float4*)pb,
                                            (const float4*)lg, (const float4*)lb,
                                            (const float4*)cls, psc);

    dim3 grid((SD4_ + 255) / 256, B_);   // (577, 64) — proven config
    add_pos_kernel<<<grid, 256>>>((const float4*)x, (float4*)d_out);
}

// round 11
// speedup vs baseline: 1.0839x; 1.0112x over previous
#include <cuda_runtime.h>
#include <math.h>

// Problem shape (fixed by setup_inputs): B=64, H=W=24, D=1024, S=577
#define B_   64
#define H_   24
#define W_   24
#define D_   1024
#define S_   (1 + H_*W_)          // 577
#define SD_  (S_ * D_)            // 590848
#define SD4_ (SD_ / 4)            // 147712 = 577 * 256 exactly

#define OMEGA1 2.62205755429212
#define LIM_T  5000.0f
#define LIM_WP 10000.0f
#define NEAR_  1.5e-7f

// Positional table scratch: [S, D] floats (already scaled by pos_scale)
__device__ float g_pos[SD_];

// Warp allreduce (butterfly): every lane ends with the full sum.
__device__ __forceinline__ float warp_allreduce(float v) {
    #pragma unroll
    for (int o = 16; o > 0; o >>= 1) v += __shfl_xor_sync(0xffffffffu, v, o);
    return v;
}

// One WARP builds one pos row. No __syncthreads anywhere.
// grid = 73 blocks x 256 threads = 584 warps (last 7 idle), rows 0..576.
__global__ __launch_bounds__(256)
void build_pos_kernel(const float* __restrict__ log_alpha_scale,
                      const float* __restrict__ alpha_learn,
                      const float4* __restrict__ proj_w,   // [4, D] as float4
                      const float4* __restrict__ proj_b,
                      const float4* __restrict__ ln_g,
                      const float4* __restrict__ ln_b,
                      const float4* __restrict__ cls_pos,
                      const float* __restrict__ pos_scale)
{
    const int warp = (blockIdx.x * 256 + threadIdx.x) >> 5;   // global warp id
    const int lane = threadIdx.x & 31;
    if (warp >= S_) return;

    const float pscale = pos_scale[0];
    float4* pos4 = reinterpret_cast<float4*>(g_pos);

    if (warp == 0) {
        // cls row: D_/4 = 256 float4, 8 per lane
        #pragma unroll
        for (int i = lane; i < 256; i += 32) {
            float4 c = cls_pos[i];
            c.x *= pscale; c.y *= pscale; c.z *= pscale; c.w *= pscale;
            pos4[i] = c;
        }
        return;
    }

    const int idx = warp - 1;
    const int pr = idx / W_;
    const int pc = idx % W_;

    // omega_3p = clip(softplus(alpha_learn), 0.02, 8.0)
    float al = alpha_learn[0];
    float sp = (al > 20.0f) ? al : log1pf(expf(al));
    float omega3p = fminf(fmaxf(sp, 0.02f), 8.0f);

    const float u = (pc + 0.5f) / (float)W_;
    const float v = (pr + 0.5f) / (float)H_;
    const float zr = u * (2.0f * (float)OMEGA1) * 0.4f;
    const float zi = v * (2.0f * omega3p) * 0.4f;

    // Lattice sum over m,n in [-12,12] \ {(0,0)}: 624 points, ~20 per lane
    float s1r = 0.f, s1i = 0.f, s2r = 0.f, s2i = 0.f;
    for (int k = lane; k < 625; k += 32) {
        int m = k / 25 - 12;
        int n = k % 25 - 12;
        if (m == 0 && n == 0) continue;
        float wr = 2.0f * (float)m * (float)OMEGA1;
        float wi = 2.0f * (float)n * (float)OMEGA1;
        float dr = zr - wr, di = zi - wi;
        float n2 = dr * dr + di * di;
        if (n2 <= NEAR_ * NEAR_) continue;   // reference mask (never active)
        float inv  = 1.0f / n2;
        float inv2 = inv * inv;
        float d2r = dr * dr - di * di;
        float d2i = 2.0f * dr * di;
        float t1r = d2r * inv2;
        float t1i = -d2i * inv2;
        float wn2 = wr * wr + wi * wi;
        float winv2 = 1.0f / (wn2 * wn2);
        t1r -= (wr * wr - wi * wi) * winv2;
        t1i += (2.0f * wr * wi) * winv2;
        t1r = fminf(fmaxf(t1r, -LIM_T), LIM_T);
        t1i = fminf(fmaxf(t1i, -LIM_T), LIM_T);
        float d3r = d2r * dr - d2i * di;
        float d3i = d2r * di + d2i * dr;
        float inv3 = inv2 * inv;
        float t2r = -2.0f * d3r * inv3;
        float t2i =  2.0f * d3i * inv3;
        t2r = fminf(fmaxf(t2r, -LIM_T), LIM_T);
        t2i = fminf(fmaxf(t2i, -LIM_T), LIM_T);
        s1r += t1r; s1i += t1i;
        s2r += t2r; s2i += t2i;
    }
    s1r = warp_allreduce(s1r);
    s1i = warp_allreduce(s1i);
    s2r = warp_allreduce(s2r);
    s2i = warp_allreduce(s2i);

    // Finish wp / wp' (every lane computes the same values — cheap)
    float zn2 = zr * zr + zi * zi;          // z != 0 for all patch rows
    float zinv  = 1.0f / zn2;
    float zinv2 = zinv * zinv;
    float z2r = zr * zr - zi * zi;
    float z2i = 2.0f * zr * zi;
    float wpr = z2r * zinv2 + s1r;
    float wpi = -z2i * zinv2 + s1i;
    float z3r = z2r * zr - z2i * zi;
    float z3i = z2r * zi + z2i * zr;
    float zinv3 = zinv2 * zinv;
    float wppr = -2.0f * z3r * zinv3 + s2r;
    float wppi =  2.0f * z3i * zinv3 + s2i;

    wpr  = fminf(fmaxf(wpr,  -LIM_WP), LIM_WP);
    wpi  = fminf(fmaxf(wpi,  -LIM_WP), LIM_WP);
    wppr = fminf(fmaxf(wppr, -LIM_WP), LIM_WP);
    wppi = fminf(fmaxf(wppi, -LIM_WP), LIM_WP);

    float alpha = fminf(fmaxf(expf(log_alpha_scale[0]), 0.002f), 0.8f);
    const float f0 = tanhf(alpha * wpr);
    const float f1 = tanhf(alpha * wpi);
    const float f2 = tanhf(alpha * wppr);
    const float f3 = tanhf(alpha * wppi);

    // Projection: p = feats @ proj_w + proj_b.  Each lane owns 8 float4 chunks.
    float4 preg[8];
    float lsum = 0.f, lsq = 0.f;
    #pragma unroll
    for (int c = 0; c < 8; ++c) {
        int i = c * 32 + lane;               // float4 index in [0,256)
        float4 w0 = proj_w[i];
        float4 w1 = proj_w[256 + i];
        float4 w2 = proj_w[512 + i];
        float4 w3 = proj_w[768 + i];
        float4 bb = proj_b[i];
        float4 p;
        p.x = f0 * w0.x + f1 * w1.x + f2 * w2.x + f3 * w3.x + bb.x;
        p.y = f0 * w0.y + f1 * w1.y + f2 * w2.y + f3 * w3.y + bb.y;
        p.z = f0 * w0.z + f1 * w1.z + f2 * w2.z + f3 * w3.z + bb.z;
        p.w = f0 * w0.w + f1 * w1.w + f2 * w2.w + f3 * w3.w + bb.w;
        preg[c] = p;
        lsum += p.x + p.y + p.z + p.w;
        lsq  += p.x * p.x + p.y * p.y + p.z * p.z + p.w * p.w;
    }
    lsum = warp_allreduce(lsum);
    lsq  = warp_allreduce(lsq);
    float mean = lsum * (1.0f / D_);
    float var  = lsq * (1.0f / D_) - mean * mean;
    float rstd = rsqrtf(var + 1e-5f);

    float4* outrow = pos4 + warp * 256;
    #pragma unroll
    for (int c = 0; c < 8; ++c) {
        int i = c * 32 + lane;
        float4 g = ln_g[i];
        float4 b = ln_b[i];
        float4 p = preg[c];
        float4 o;
        o.x = ((p.x - mean) * rstd * g.x + b.x) * pscale;
        o.y = ((p.y - mean) * rstd * g.y + b.y) * pscale;
        o.z = ((p.z - mean) * rstd * g.z + b.z) * pscale;
        o.w = ((p.w - mean) * rstd * g.w + b.w) * pscale;
        outrow[i] = o;
    }
}

// Streaming add, 2 batches per block: front-batched loads (MLP=2) and one
// shared pos read. grid (577, 32).
__global__ __launch_bounds__(256)
void add_pos_kernel(const float4* __restrict__ x, float4* __restrict__ out)
{
    const int i = blockIdx.x * 256 + threadIdx.x;   // float4 index within a batch
    const long long g0 = (long long)(blockIdx.y * 2)     * SD4_ + i;
    const long long g1 = (long long)(blockIdx.y * 2 + 1) * SD4_ + i;
    float4 x0 = __ldcs(x + g0);
    float4 x1 = __ldcs(x + g1);
    float4 pv = reinterpret_cast<const float4*>(g_pos)[i];
    x0.x += pv.x; x0.y += pv.y; x0.z += pv.z; x0.w += pv.w;
    x1.x += pv.x; x1.y += pv.y; x1.z += pv.z; x1.w += pv.w;
    __stcs(out + g0, x0);
    __stcs(out + g1, x1);
}

extern "C" void kernel_launch(void* const* d_in, const int* in_sizes, int n_in,
                              void* d_out, int out_size)
{
    // metadata order: x, h, w, log_alpha_scale, alpha_learn, proj_w, proj_b,
    //                 ln_g, ln_b, cls_pos, pos_scale
    const float* x    = (const float*)d_in[0];
    const float* las  = (const float*)d_in[3];
    const float* al   = (const float*)d_in[4];
    const float* pw   = (const float*)d_in[5];
    const float* pb   = (const float*)d_in[6];
    const float* lg   = (const float*)d_in[7];
    const float* lb   = (const float*)d_in[8];
    const float* cls  = (const float*)d_in[9];
    const float* psc  = (const float*)d_in[10];

    // 577 rows, one warp each: 73 blocks x 8 warps
    build_pos_kernel<<<(S_ + 7) / 8, 256>>>(las, al,
                                            (const float4*)pw, (const float4*)pb,
                                            (const float4*)lg, (const float4*)lb,
                                            (const float4*)cls, psc);

    dim3 grid(SD4_ / 256, B_ / 2);   // (577, 32), SD4_ = 577*256 exactly
    add_pos_kernel<<<grid, 256>>>((const float4*)x, (float4*)d_out);
}